// round 2
// baseline (speedup 1.0000x reference)
#include <cuda_runtime.h>
#include <math.h>

#define Bb 16
#define Nn 1024
#define Cc 768
#define Ee 8
#define Hh 192
#define Kk 2

// Persistent device scratch (no allocations allowed)
__device__ float g_sums[Bb * Ee];
__device__ int   g_sel[Bb * Kk];
__device__ float g_gate[Bb * Kk];
__device__ float g_h[(size_t)Bb * Kk * Nn * Hh];   // 25.2 MB fp32

// ---------------------------------------------------------------------------
// 0) zero the per-(b,e) logit sums every launch (graph replays reuse globals)
// ---------------------------------------------------------------------------
__global__ void zero_sums_kernel() {
    int i = threadIdx.x;
    if (i < Bb * Ee) g_sums[i] = 0.0f;
}

// ---------------------------------------------------------------------------
// 1) gate: per-b skinny GEMM x[b] @ gate_w[task] -> 16 logits per (b,n),
//    fused softplus/noise, accumulate sum over n into g_sums[b][e].
//    grid (16 n-tiles, 16 b), 256 threads; gate_w[t] resident in smem [e][c].
// ---------------------------------------------------------------------------
__global__ void gate_kernel(const float* __restrict__ x,
                            const int*   __restrict__ task_ids,
                            const float* __restrict__ eps,
                            const float* __restrict__ gate_w) {
    __shared__ float sgw[16][Cc];   // 48 KB, [e][c]: warp reads consecutive c -> no conflicts
    const int b = blockIdx.y;
    const int t = task_ids[b];
    const float* gwt = gate_w + (size_t)t * Cc * 16;   // [c][e] in global
    for (int idx = threadIdx.x; idx < 16 * Cc; idx += blockDim.x) {
        int c = idx >> 4, e = idx & 15;
        sgw[e][c] = gwt[idx];
    }
    __syncthreads();

    const int warp = threadIdx.x >> 5;
    const int lane = threadIdx.x & 31;
    const int n_base = blockIdx.x * 64 + warp * 8;   // 8 warps x 8 rows

    float wacc = 0.0f;   // lane<8: running sum of contrib for expert=lane

    for (int r = 0; r < 8; r += 2) {
        const int n0 = n_base + r;
        const float* x0 = x + ((size_t)b * Nn + n0) * Cc;
        const float* x1 = x0 + Cc;
        float a0[16], a1[16];
        #pragma unroll
        for (int e = 0; e < 16; e++) { a0[e] = 0.f; a1[e] = 0.f; }

        for (int c0 = 0; c0 < Cc; c0 += 32) {
            float xv0 = x0[c0 + lane];
            float xv1 = x1[c0 + lane];
            #pragma unroll
            for (int e = 0; e < 16; e++) {
                float g = sgw[e][c0 + lane];
                a0[e] += xv0 * g;
                a1[e] += xv1 * g;
            }
        }
        // butterfly reduce each accumulator across the warp
        #pragma unroll
        for (int e = 0; e < 16; e++) {
            #pragma unroll
            for (int off = 16; off; off >>= 1) {
                a0[e] += __shfl_xor_sync(0xffffffffu, a0[e], off);
                a1[e] += __shfl_xor_sync(0xffffffffu, a1[e], off);
            }
        }
        if (lane < 8) {
            // row n0
            float raw0 = a0[lane + 8];
            float sp0  = (raw0 > 20.0f) ? raw0 : log1pf(expf(raw0));
            float c0v  = a0[lane] + eps[((size_t)b * Nn + n0) * Ee + lane] * (sp0 + 0.01f);
            // row n0+1
            float raw1 = a1[lane + 8];
            float sp1  = (raw1 > 20.0f) ? raw1 : log1pf(expf(raw1));
            float c1v  = a1[lane] + eps[((size_t)b * Nn + n0 + 1) * Ee + lane] * (sp1 + 0.01f);
            wacc += c0v + c1v;
        }
    }
    if (lane < 8) atomicAdd(&g_sums[b * Ee + lane], wacc);
}

// ---------------------------------------------------------------------------
// 2) top-2 + gate values per batch
// ---------------------------------------------------------------------------
__global__ void topk_kernel() {
    int b = threadIdx.x;
    if (b >= Bb) return;
    float s[Ee];
    #pragma unroll
    for (int e = 0; e < Ee; e++) s[e] = g_sums[b * Ee + e];

    int i1 = 0; float v1 = s[0];
    #pragma unroll
    for (int e = 1; e < Ee; e++) if (s[e] > v1) { v1 = s[e]; i1 = e; }
    int i2 = -1; float v2 = -3.4e38f;
    #pragma unroll
    for (int e = 0; e < Ee; e++) if (e != i1 && s[e] > v2) { v2 = s[e]; i2 = e; }

    // scaled = [(v1-v2)/(v1-v2+1e-6), 0]; softmax over the two
    float d   = v1 - v2;
    float sc1 = d / (d + 1e-6f);
    float mx  = fmaxf(sc1, 0.0f);
    float e1  = expf(sc1 - mx);
    float e2  = expf(0.0f - mx);
    float inv = 1.0f / (e1 + e2);

    g_sel[b * 2 + 0]  = i1;
    g_sel[b * 2 + 1]  = i2;
    g_gate[b * 2 + 0] = e1 * inv;
    g_gate[b * 2 + 1] = e2 * inv;
}

// ---------------------------------------------------------------------------
// 3) fc1 + gelu for the 2 selected experts per batch
//    per (b,slot): [1024x768] @ [192x768]^T, both K-major (TN form)
// ---------------------------------------------------------------------------
#define BM 64
#define BN 64
#define BKk 32

__global__ void fc1_kernel(const float* __restrict__ x,
                           const float* __restrict__ w1,
                           const float* __restrict__ b1) {
    const int bs = blockIdx.z;
    const int b = bs >> 1, slot = bs & 1;
    const int e = g_sel[b * 2 + slot];
    const float* A  = x  + (size_t)b * Nn * Cc;   // [1024][768]
    const float* Bw = w1 + (size_t)e * Hh * Cc;   // [192][768]
    const int m0 = blockIdx.y * BM;
    const int n0 = blockIdx.x * BN;

    __shared__ float As[BKk][BM + 4];
    __shared__ float Bs[BKk][BN + 4];

    const int tid = threadIdx.x;
    const int tx = tid & 15, ty = tid >> 4;

    float acc[4][4];
    #pragma unroll
    for (int i = 0; i < 4; i++)
        #pragma unroll
        for (int j = 0; j < 4; j++) acc[i][j] = 0.f;

    for (int k0 = 0; k0 < Cc; k0 += BKk) {
        #pragma unroll
        for (int l = 0; l < 2; l++) {
            int li  = tid + l * 256;          // 0..511 float4 slots
            int row = li >> 3;                // 64 rows
            int kq  = (li & 7) << 2;          // 8 float4 per row
            float4 va = *(const float4*)&A[(size_t)(m0 + row) * Cc + k0 + kq];
            As[kq + 0][row] = va.x; As[kq + 1][row] = va.y;
            As[kq + 2][row] = va.z; As[kq + 3][row] = va.w;
            float4 vb = *(const float4*)&Bw[(size_t)(n0 + row) * Cc + k0 + kq];
            Bs[kq + 0][row] = vb.x; Bs[kq + 1][row] = vb.y;
            Bs[kq + 2][row] = vb.z; Bs[kq + 3][row] = vb.w;
        }
        __syncthreads();

        #pragma unroll 8
        for (int k = 0; k < BKk; k++) {
            float ra[4], rb[4];
            #pragma unroll
            for (int i = 0; i < 4; i++) ra[i] = As[k][ty * 4 + i];
            #pragma unroll
            for (int j = 0; j < 4; j++) rb[j] = Bs[k][tx * 4 + j];
            #pragma unroll
            for (int i = 0; i < 4; i++)
                #pragma unroll
                for (int j = 0; j < 4; j++) acc[i][j] += ra[i] * rb[j];
        }
        __syncthreads();
    }

    float* hout = g_h + (((size_t)b * 2 + slot) * Nn) * Hh;
    #pragma unroll
    for (int i = 0; i < 4; i++) {
        int m = m0 + ty * 4 + i;
        #pragma unroll
        for (int j = 0; j < 4; j++) {
            int n = n0 + tx * 4 + j;
            float v = acc[i][j] + b1[e * Hh + n];
            v = 0.5f * v * (1.0f + erff(v * 0.70710678118654752f));  // exact gelu
            hout[(size_t)m * Hh + n] = v;
        }
    }
}

// ---------------------------------------------------------------------------
// 4) fc2 over both slots (gate folded into B-tile), + bias, + residual x
//    per b: [1024x192] @ [768x192]^T twice, accumulated
// ---------------------------------------------------------------------------
__global__ void fc2_kernel(const float* __restrict__ x,
                           const float* __restrict__ w2,
                           const float* __restrict__ b2,
                           float* __restrict__ out) {
    const int b  = blockIdx.z;
    const int m0 = blockIdx.y * BM;   // n (token) dim
    const int n0 = blockIdx.x * BN;   // c (channel) dim
    const int sel0 = g_sel[b * 2], sel1 = g_sel[b * 2 + 1];
    const float gt0 = g_gate[b * 2], gt1 = g_gate[b * 2 + 1];

    __shared__ float As[BKk][BM + 4];
    __shared__ float Bs[BKk][BN + 4];

    const int tid = threadIdx.x;
    const int tx = tid & 15, ty = tid >> 4;

    float acc[4][4];
    #pragma unroll
    for (int i = 0; i < 4; i++)
        #pragma unroll
        for (int j = 0; j < 4; j++) acc[i][j] = 0.f;

    for (int kk = 0; kk < 12; kk++) {          // 2 slots x (192/32) tiles
        const int slot = kk / 6;
        const int k0   = (kk % 6) * BKk;
        const int e    = slot ? sel1 : sel0;
        const float gt = slot ? gt1  : gt0;
        const float* A  = g_h + (((size_t)b * 2 + slot) * Nn) * Hh;  // [1024][192]
        const float* Bw = w2  + (size_t)e * Cc * Hh;                  // [768][192]

        #pragma unroll
        for (int l = 0; l < 2; l++) {
            int li  = tid + l * 256;
            int row = li >> 3;
            int kq  = (li & 7) << 2;
            float4 va = *(const float4*)&A[(size_t)(m0 + row) * Hh + k0 + kq];
            As[kq + 0][row] = va.x; As[kq + 1][row] = va.y;
            As[kq + 2][row] = va.z; As[kq + 3][row] = va.w;
            float4 vb = *(const float4*)&Bw[(size_t)(n0 + row) * Hh + k0 + kq];
            Bs[kq + 0][row] = gt * vb.x; Bs[kq + 1][row] = gt * vb.y;
            Bs[kq + 2][row] = gt * vb.z; Bs[kq + 3][row] = gt * vb.w;
        }
        __syncthreads();

        #pragma unroll 8
        for (int k = 0; k < BKk; k++) {
            float ra[4], rb[4];
            #pragma unroll
            for (int i = 0; i < 4; i++) ra[i] = As[k][ty * 4 + i];
            #pragma unroll
            for (int j = 0; j < 4; j++) rb[j] = Bs[k][tx * 4 + j];
            #pragma unroll
            for (int i = 0; i < 4; i++)
                #pragma unroll
                for (int j = 0; j < 4; j++) acc[i][j] += ra[i] * rb[j];
        }
        __syncthreads();
    }

    #pragma unroll
    for (int i = 0; i < 4; i++) {
        int m = m0 + ty * 4 + i;
        const float* xrow = x + ((size_t)b * Nn + m) * Cc;
        float* orow = out + ((size_t)b * Nn + m) * Cc;
        #pragma unroll
        for (int j = 0; j < 4; j++) {
            int n = n0 + tx * 4 + j;
            float bias = gt0 * b2[sel0 * Cc + n] + gt1 * b2[sel1 * Cc + n];
            orow[n] = xrow[n] + acc[i][j] + bias;
        }
    }
}

// ---------------------------------------------------------------------------
extern "C" void kernel_launch(void* const* d_in, const int* in_sizes, int n_in,
                              void* d_out, int out_size) {
    const float* x        = (const float*)d_in[0];
    const int*   task_ids = (const int*)  d_in[1];
    const float* eps      = (const float*)d_in[2];
    const float* gate_w   = (const float*)d_in[3];
    const float* fc1_w    = (const float*)d_in[4];
    const float* fc1_b    = (const float*)d_in[5];
    const float* fc2_w    = (const float*)d_in[6];
    const float* fc2_b    = (const float*)d_in[7];
    float* out = (float*)d_out;

    zero_sums_kernel<<<1, 128>>>();
    gate_kernel<<<dim3(Nn / 64, Bb), 256>>>(x, task_ids, eps, gate_w);
    topk_kernel<<<1, 32>>>();
    fc1_kernel<<<dim3(Hh / BN, Nn / BM, Bb * Kk), 256>>>(x, fc1_w, fc1_b);
    fc2_kernel<<<dim3(Cc / BN, Nn / BM, Bb), 256>>>(x, fc2_w, fc2_b, out);
}

// round 3
// speedup vs baseline: 1.9124x; 1.9124x over previous
#include <cuda_runtime.h>
#include <math.h>

#define Bb 16
#define Nn 1024
#define Cc 768
#define Ee 8
#define Hh 192
#define Kk 2

// Persistent device scratch (no allocations allowed)
__device__ float g_sums[Bb * Ee];
__device__ int   g_sel[Bb * Kk];
__device__ float g_gate[Bb * Kk];
__device__ float g_h[(size_t)Bb * Kk * Nn * Hh];   // 25.2 MB fp32 (post-gelu)

__device__ __forceinline__ unsigned f2tf32(float f) {
    unsigned r;
    asm("cvt.rna.tf32.f32 %0, %1;" : "=r"(r) : "f"(f));
    return r;
}

__device__ __forceinline__ void mma_tf32(float& c0, float& c1, float& c2, float& c3,
                                         unsigned a0, unsigned a1, unsigned a2, unsigned a3,
                                         unsigned b0, unsigned b1) {
    asm volatile(
        "mma.sync.aligned.m16n8k8.row.col.f32.tf32.tf32.f32 "
        "{%0,%1,%2,%3},{%4,%5,%6,%7},{%8,%9},{%0,%1,%2,%3};"
        : "+f"(c0), "+f"(c1), "+f"(c2), "+f"(c3)
        : "r"(a0), "r"(a1), "r"(a2), "r"(a3), "r"(b0), "r"(b1));
}

// ---------------------------------------------------------------------------
// 0) zero per-(b,e) logit sums each launch (graph replays reuse globals)
// ---------------------------------------------------------------------------
__global__ void zero_sums_kernel() {
    int i = threadIdx.x;
    if (i < Bb * Ee) g_sums[i] = 0.0f;
}

// ---------------------------------------------------------------------------
// 1) gate: per-b skinny GEMM + softplus/noise, sum over n into g_sums
// ---------------------------------------------------------------------------
__global__ void gate_kernel(const float* __restrict__ x,
                            const int*   __restrict__ task_ids,
                            const float* __restrict__ eps,
                            const float* __restrict__ gate_w) {
    __shared__ float sgw[16][Cc];
    const int b = blockIdx.y;
    const int t = task_ids[b];
    const float* gwt = gate_w + (size_t)t * Cc * 16;
    for (int idx = threadIdx.x; idx < 16 * Cc; idx += blockDim.x) {
        int c = idx >> 4, e = idx & 15;
        sgw[e][c] = gwt[idx];
    }
    __syncthreads();

    const int warp = threadIdx.x >> 5;
    const int lane = threadIdx.x & 31;
    const int n_base = blockIdx.x * 64 + warp * 8;

    float wacc = 0.0f;

    for (int r = 0; r < 8; r += 2) {
        const int n0 = n_base + r;
        const float* x0 = x + ((size_t)b * Nn + n0) * Cc;
        const float* x1 = x0 + Cc;
        float a0[16], a1[16];
        #pragma unroll
        for (int e = 0; e < 16; e++) { a0[e] = 0.f; a1[e] = 0.f; }

        for (int c0 = 0; c0 < Cc; c0 += 32) {
            float xv0 = x0[c0 + lane];
            float xv1 = x1[c0 + lane];
            #pragma unroll
            for (int e = 0; e < 16; e++) {
                float g = sgw[e][c0 + lane];
                a0[e] += xv0 * g;
                a1[e] += xv1 * g;
            }
        }
        #pragma unroll
        for (int e = 0; e < 16; e++) {
            #pragma unroll
            for (int off = 16; off; off >>= 1) {
                a0[e] += __shfl_xor_sync(0xffffffffu, a0[e], off);
                a1[e] += __shfl_xor_sync(0xffffffffu, a1[e], off);
            }
        }
        if (lane < 8) {
            float raw0 = a0[lane + 8];
            float sp0  = (raw0 > 20.0f) ? raw0 : log1pf(expf(raw0));
            float c0v  = a0[lane] + eps[((size_t)b * Nn + n0) * Ee + lane] * (sp0 + 0.01f);
            float raw1 = a1[lane + 8];
            float sp1  = (raw1 > 20.0f) ? raw1 : log1pf(expf(raw1));
            float c1v  = a1[lane] + eps[((size_t)b * Nn + n0 + 1) * Ee + lane] * (sp1 + 0.01f);
            wacc += c0v + c1v;
        }
    }
    if (lane < 8) atomicAdd(&g_sums[b * Ee + lane], wacc);
}

// ---------------------------------------------------------------------------
// 2) top-2 + gate values per batch
// ---------------------------------------------------------------------------
__global__ void topk_kernel() {
    int b = threadIdx.x;
    if (b >= Bb) return;
    float s[Ee];
    #pragma unroll
    for (int e = 0; e < Ee; e++) s[e] = g_sums[b * Ee + e];

    int i1 = 0; float v1 = s[0];
    #pragma unroll
    for (int e = 1; e < Ee; e++) if (s[e] > v1) { v1 = s[e]; i1 = e; }
    int i2 = -1; float v2 = -3.4e38f;
    #pragma unroll
    for (int e = 0; e < Ee; e++) if (e != i1 && s[e] > v2) { v2 = s[e]; i2 = e; }

    float d   = v1 - v2;
    float sc1 = d / (d + 1e-6f);
    float mx  = fmaxf(sc1, 0.0f);
    float e1  = expf(sc1 - mx);
    float e2  = expf(0.0f - mx);
    float inv = 1.0f / (e1 + e2);

    g_sel[b * 2 + 0]  = i1;
    g_sel[b * 2 + 1]  = i2;
    g_gate[b * 2 + 0] = e1 * inv;
    g_gate[b * 2 + 1] = e2 * inv;
}

// ---------------------------------------------------------------------------
// 3) fc1 + gelu, tf32 tensor cores.  Per (b,slot): [1024x768]@[192x768]^T.
//    Block tile 64x192 (full H), K-chunks of 16. 8 warps = 2(m) x 4(n),
//    warp tile 32x48 -> 2 m-frags x 6 n-frags of m16n8k8.
// ---------------------------------------------------------------------------
#define F1_BM 64
#define F1_AS 72    // 72 % 32 == 8 -> conflict-free frag LDS
#define F1_BS 200   // 200 % 32 == 8

__global__ void fc1_kernel(const float* __restrict__ x,
                           const float* __restrict__ w1,
                           const float* __restrict__ b1v) {
    const int bs = blockIdx.z;
    const int b = bs >> 1, slot = bs & 1;
    const int e = g_sel[b * 2 + slot];
    const float* A  = x  + (size_t)b * Nn * Cc;   // [1024][768]
    const float* Bw = w1 + (size_t)e * Hh * Cc;   // [192][768]
    const int m0 = blockIdx.y * F1_BM;

    __shared__ unsigned As[16][F1_AS];   // [k][m]
    __shared__ unsigned Bs[16][F1_BS];   // [k][n]

    const int tid  = threadIdx.x;
    const int wid  = tid >> 5;
    const int lane = tid & 31;
    const int gid  = lane >> 2;
    const int tig  = lane & 3;
    const int warp_m = wid >> 2;   // 0..1
    const int warp_n = wid & 3;    // 0..3

    float acc[2][6][4];
    #pragma unroll
    for (int i = 0; i < 2; i++)
        #pragma unroll
        for (int j = 0; j < 6; j++)
            #pragma unroll
            for (int q = 0; q < 4; q++) acc[i][j][q] = 0.f;

    const int arow = tid >> 2;          // 0..63
    const int akq  = (tid & 3) << 2;    // 0,4,8,12

    for (int k0 = 0; k0 < Cc; k0 += 16) {
        // A: 64x16 -> 256 float4
        {
            float4 v = *(const float4*)&A[(size_t)(m0 + arow) * Cc + k0 + akq];
            As[akq + 0][arow] = f2tf32(v.x);
            As[akq + 1][arow] = f2tf32(v.y);
            As[akq + 2][arow] = f2tf32(v.z);
            As[akq + 3][arow] = f2tf32(v.w);
        }
        // B: 192x16 -> 768 float4
        #pragma unroll
        for (int l = 0; l < 3; l++) {
            int idx  = tid + l * 256;
            int brow = idx >> 2;           // 0..191
            int bkq  = (idx & 3) << 2;
            float4 v = *(const float4*)&Bw[(size_t)brow * Cc + k0 + bkq];
            Bs[bkq + 0][brow] = f2tf32(v.x);
            Bs[bkq + 1][brow] = f2tf32(v.y);
            Bs[bkq + 2][brow] = f2tf32(v.z);
            Bs[bkq + 3][brow] = f2tf32(v.w);
        }
        __syncthreads();

        #pragma unroll
        for (int ks = 0; ks < 16; ks += 8) {
            unsigned af[2][4];
            #pragma unroll
            for (int mi = 0; mi < 2; mi++) {
                int mrow = warp_m * 32 + mi * 16 + gid;
                af[mi][0] = As[ks + tig    ][mrow];
                af[mi][1] = As[ks + tig    ][mrow + 8];
                af[mi][2] = As[ks + tig + 4][mrow];
                af[mi][3] = As[ks + tig + 4][mrow + 8];
            }
            unsigned bf[6][2];
            #pragma unroll
            for (int ni = 0; ni < 6; ni++) {
                int ncol = warp_n * 48 + ni * 8 + gid;
                bf[ni][0] = Bs[ks + tig    ][ncol];
                bf[ni][1] = Bs[ks + tig + 4][ncol];
            }
            #pragma unroll
            for (int mi = 0; mi < 2; mi++)
                #pragma unroll
                for (int ni = 0; ni < 6; ni++)
                    mma_tf32(acc[mi][ni][0], acc[mi][ni][1], acc[mi][ni][2], acc[mi][ni][3],
                             af[mi][0], af[mi][1], af[mi][2], af[mi][3],
                             bf[ni][0], bf[ni][1]);
        }
        __syncthreads();
    }

    // Epilogue: + bias, exact gelu, store to g_h
    float* hout = g_h + (((size_t)b * 2 + slot) * Nn) * Hh;
    #pragma unroll
    for (int ni = 0; ni < 6; ni++) {
        int col = warp_n * 48 + ni * 8 + 2 * tig;
        float bia0 = b1v[e * Hh + col];
        float bia1 = b1v[e * Hh + col + 1];
        #pragma unroll
        for (int mi = 0; mi < 2; mi++) {
            int r0 = m0 + warp_m * 32 + mi * 16 + gid;
            float v0 = acc[mi][ni][0] + bia0;
            float v1 = acc[mi][ni][1] + bia1;
            float v2 = acc[mi][ni][2] + bia0;
            float v3 = acc[mi][ni][3] + bia1;
            v0 = 0.5f * v0 * (1.0f + erff(v0 * 0.70710678118654752f));
            v1 = 0.5f * v1 * (1.0f + erff(v1 * 0.70710678118654752f));
            v2 = 0.5f * v2 * (1.0f + erff(v2 * 0.70710678118654752f));
            v3 = 0.5f * v3 * (1.0f + erff(v3 * 0.70710678118654752f));
            *(float2*)&hout[(size_t)r0 * Hh + col]       = make_float2(v0, v1);
            *(float2*)&hout[(size_t)(r0 + 8) * Hh + col] = make_float2(v2, v3);
        }
    }
}

// ---------------------------------------------------------------------------
// 4) fc2 (tf32 tensor cores) over both slots + bias + residual.
//    Per b: [1024x192]@[768x192]^T x2 accumulated. Block 64x128,
//    8 warps = 2x4, warp tile 32x32 -> 2 m-frags x 4 n-frags.
// ---------------------------------------------------------------------------
#define F2_AS 72
#define F2_BS 136   // 136 % 32 == 8

__global__ void fc2_kernel(const float* __restrict__ x,
                           const float* __restrict__ w2,
                           const float* __restrict__ b2,
                           float* __restrict__ out) {
    const int b  = blockIdx.z;
    const int m0 = blockIdx.y * 64;
    const int n0 = blockIdx.x * 128;
    const int sel0 = g_sel[b * 2], sel1 = g_sel[b * 2 + 1];
    const float gt0 = g_gate[b * 2], gt1 = g_gate[b * 2 + 1];

    __shared__ unsigned As[16][F2_AS];
    __shared__ unsigned Bs[16][F2_BS];

    const int tid  = threadIdx.x;
    const int wid  = tid >> 5;
    const int lane = tid & 31;
    const int gid  = lane >> 2;
    const int tig  = lane & 3;
    const int warp_m = wid >> 2;   // 0..1
    const int warp_n = wid & 3;    // 0..3

    float acc[2][4][4];
    #pragma unroll
    for (int i = 0; i < 2; i++)
        #pragma unroll
        for (int j = 0; j < 4; j++)
            #pragma unroll
            for (int q = 0; q < 4; q++) acc[i][j][q] = 0.f;

    const int arow = tid >> 2;
    const int akq  = (tid & 3) << 2;

    for (int kk = 0; kk < 24; kk++) {          // 2 slots x 12 k-chunks
        const int slot = kk / 12;
        const int kc   = (kk % 12) * 16;
        const int e    = slot ? sel1 : sel0;
        const float gt = slot ? gt1  : gt0;
        const float* Ah = g_h + (((size_t)b * 2 + slot) * Nn) * Hh;  // [1024][192]
        const float* Bw = w2  + (size_t)e * Cc * Hh;                  // [768][192]

        {
            float4 v = *(const float4*)&Ah[(size_t)(m0 + arow) * Hh + kc + akq];
            As[akq + 0][arow] = f2tf32(v.x);
            As[akq + 1][arow] = f2tf32(v.y);
            As[akq + 2][arow] = f2tf32(v.z);
            As[akq + 3][arow] = f2tf32(v.w);
        }
        #pragma unroll
        for (int l = 0; l < 2; l++) {
            int idx  = tid + l * 256;
            int brow = idx >> 2;            // 0..127
            int bkq  = (idx & 3) << 2;
            float4 v = *(const float4*)&Bw[(size_t)(n0 + brow) * Hh + kc + bkq];
            Bs[bkq + 0][brow] = f2tf32(gt * v.x);
            Bs[bkq + 1][brow] = f2tf32(gt * v.y);
            Bs[bkq + 2][brow] = f2tf32(gt * v.z);
            Bs[bkq + 3][brow] = f2tf32(gt * v.w);
        }
        __syncthreads();

        #pragma unroll
        for (int ks = 0; ks < 16; ks += 8) {
            unsigned af[2][4];
            #pragma unroll
            for (int mi = 0; mi < 2; mi++) {
                int mrow = warp_m * 32 + mi * 16 + gid;
                af[mi][0] = As[ks + tig    ][mrow];
                af[mi][1] = As[ks + tig    ][mrow + 8];
                af[mi][2] = As[ks + tig + 4][mrow];
                af[mi][3] = As[ks + tig + 4][mrow + 8];
            }
            unsigned bf[4][2];
            #pragma unroll
            for (int ni = 0; ni < 4; ni++) {
                int ncol = warp_n * 32 + ni * 8 + gid;
                bf[ni][0] = Bs[ks + tig    ][ncol];
                bf[ni][1] = Bs[ks + tig + 4][ncol];
            }
            #pragma unroll
            for (int mi = 0; mi < 2; mi++)
                #pragma unroll
                for (int ni = 0; ni < 4; ni++)
                    mma_tf32(acc[mi][ni][0], acc[mi][ni][1], acc[mi][ni][2], acc[mi][ni][3],
                             af[mi][0], af[mi][1], af[mi][2], af[mi][3],
                             bf[ni][0], bf[ni][1]);
        }
        __syncthreads();
    }

    // Epilogue: + gated biases + residual
    #pragma unroll
    for (int ni = 0; ni < 4; ni++) {
        int col = n0 + warp_n * 32 + ni * 8 + 2 * tig;
        float bia0 = gt0 * b2[sel0 * Cc + col]     + gt1 * b2[sel1 * Cc + col];
        float bia1 = gt0 * b2[sel0 * Cc + col + 1] + gt1 * b2[sel1 * Cc + col + 1];
        #pragma unroll
        for (int mi = 0; mi < 2; mi++) {
            int r0 = m0 + warp_m * 32 + mi * 16 + gid;
            {
                float2 xv = *(const float2*)&x[((size_t)b * Nn + r0) * Cc + col];
                *(float2*)&out[((size_t)b * Nn + r0) * Cc + col] =
                    make_float2(xv.x + acc[mi][ni][0] + bia0,
                                xv.y + acc[mi][ni][1] + bia1);
            }
            {
                float2 xv = *(const float2*)&x[((size_t)b * Nn + r0 + 8) * Cc + col];
                *(float2*)&out[((size_t)b * Nn + r0 + 8) * Cc + col] =
                    make_float2(xv.x + acc[mi][ni][2] + bia0,
                                xv.y + acc[mi][ni][3] + bia1);
            }
        }
    }
}

// ---------------------------------------------------------------------------
extern "C" void kernel_launch(void* const* d_in, const int* in_sizes, int n_in,
                              void* d_out, int out_size) {
    const float* x        = (const float*)d_in[0];
    const int*   task_ids = (const int*)  d_in[1];
    const float* eps      = (const float*)d_in[2];
    const float* gate_w   = (const float*)d_in[3];
    const float* fc1_w    = (const float*)d_in[4];
    const float* fc1_b    = (const float*)d_in[5];
    const float* fc2_w    = (const float*)d_in[6];
    const float* fc2_b    = (const float*)d_in[7];
    float* out = (float*)d_out;

    zero_sums_kernel<<<1, 128>>>();
    gate_kernel<<<dim3(Nn / 64, Bb), 256>>>(x, task_ids, eps, gate_w);
    topk_kernel<<<1, 32>>>();
    fc1_kernel<<<dim3(1, Nn / F1_BM, Bb * Kk), 256>>>(x, fc1_w, fc1_b);
    fc2_kernel<<<dim3(Cc / 128, Nn / 64, Bb), 256>>>(x, fc2_w, fc2_b, out);
}

// round 5
// speedup vs baseline: 4.3151x; 2.2564x over previous
#include <cuda_runtime.h>
#include <cuda_bf16.h>
#include <math.h>

#define Bb 16
#define Nn 1024
#define Cc 768
#define Ee 8
#define Hh 192
#define Kk 2

// Persistent device scratch (no allocations allowed)
__device__ float    g_sums[Bb * Ee];
__device__ int      g_sel[Bb * Kk];
__device__ float    g_gate[Bb * Kk];
__device__ unsigned g_xb [Bb * Nn * Cc / 2];       // x as bf16 pairs (25 MB)
__device__ unsigned g_w1b[Ee * Hh * Cc / 2];       // fc1_w bf16
__device__ unsigned g_w2b[Ee * Cc * Hh / 2];       // fc2_w bf16
__device__ unsigned g_hb [(size_t)Bb * Kk * Nn * Hh / 2];  // gated gelu(h) bf16 (12.6 MB)

// ---------------- helpers ----------------
__device__ __forceinline__ unsigned sptr(const void* p) {
    return (unsigned)__cvta_generic_to_shared(p);
}
#define CP16(d, s) asm volatile("cp.async.cg.shared.global [%0], [%1], 16;\n" :: "r"(d), "l"(s))
#define CP_COMMIT  asm volatile("cp.async.commit_group;\n")
#define CP_WAIT1   asm volatile("cp.async.wait_group 1;\n")
#define CP_WAIT0   asm volatile("cp.async.wait_group 0;\n")

__device__ __forceinline__ unsigned pkbf(float lo, float hi) {
    unsigned u;  // d.hi = first src, d.lo = second src
    asm("cvt.rn.bf16x2.f32 %0, %1, %2;" : "=r"(u) : "f"(hi), "f"(lo));
    return u;
}

__device__ __forceinline__ void mma_bf16(float* c, const unsigned* a, const unsigned* b) {
    asm volatile(
        "mma.sync.aligned.m16n8k16.row.col.f32.bf16.bf16.f32 "
        "{%0,%1,%2,%3},{%4,%5,%6,%7},{%8,%9},{%0,%1,%2,%3};"
        : "+f"(c[0]), "+f"(c[1]), "+f"(c[2]), "+f"(c[3])
        : "r"(a[0]), "r"(a[1]), "r"(a[2]), "r"(a[3]), "r"(b[0]), "r"(b[1]));
}

__device__ __forceinline__ void mma_tf32(float* c, unsigned a0, unsigned a1, unsigned a2,
                                         unsigned a3, unsigned b0, unsigned b1) {
    asm volatile(
        "mma.sync.aligned.m16n8k8.row.col.f32.tf32.tf32.f32 "
        "{%0,%1,%2,%3},{%4,%5,%6,%7},{%8,%9},{%0,%1,%2,%3};"
        : "+f"(c[0]), "+f"(c[1]), "+f"(c[2]), "+f"(c[3])
        : "r"(a0), "r"(a1), "r"(a2), "r"(a3), "r"(b0), "r"(b1));
}

__device__ __forceinline__ float gelu_exact(float v) {
    return 0.5f * v * (1.0f + erff(v * 0.70710678118654752f));
}

// ---------------------------------------------------------------------------
// 0) prep: zero g_sums + convert fc1_w / fc2_w to bf16
// ---------------------------------------------------------------------------
__global__ void prep_kernel(const float* __restrict__ w1, const float* __restrict__ w2) {
    int i = blockIdx.x * 256 + threadIdx.x;
    if (i < Bb * Ee) g_sums[i] = 0.0f;
    const int NF4 = Ee * Hh * Cc / 4;   // 294912 float4 per weight tensor
    if (i < NF4) {
        float4 v = ((const float4*)w1)[i];
        ((uint2*)g_w1b)[i] = make_uint2(pkbf(v.x, v.y), pkbf(v.z, v.w));
    } else if (i < 2 * NF4) {
        int j = i - NF4;
        float4 v = ((const float4*)w2)[j];
        ((uint2*)g_w2b)[j] = make_uint2(pkbf(v.x, v.y), pkbf(v.z, v.w));
    }
}

// ---------------------------------------------------------------------------
// 1) gate: tf32 mma, cp.async double-buffered, emits bf16 x as side product.
//    Block = (64 n-rows, b). 128 threads, 4 warps x 16 rows. N=16 (clean|noise).
// ---------------------------------------------------------------------------
__global__ void gate_kernel(const float* __restrict__ x,
                            const int*   __restrict__ task_ids,
                            const float* __restrict__ eps,
                            const float* __restrict__ gate_w) {
    __shared__ float As[2][64][36];   // [m][k], stride 36 words: banks 4g+t conflict-free
    __shared__ float Bs[2][32][24];   // [k][e], stride 24 words: banks 24t+g conflict-free

    const int b  = blockIdx.y;
    const int m0 = blockIdx.x * 64;
    const int t_id = task_ids[b];
    const float* gwt = gate_w + (size_t)t_id * Cc * 16;
    const float* xb  = x + ((size_t)b * Nn + m0) * Cc;

    const int tid = threadIdx.x, warp = tid >> 5, lane = tid & 31;
    const int g = lane >> 2, tq = lane & 3;

    float acc[2][4] = {};

    // prologue: chunk 0
    {
        #pragma unroll
        for (int j = 0; j < 4; j++) {
            int idx = tid + j * 128, row = idx >> 3, c = idx & 7;
            CP16(sptr(&As[0][row][c * 4]), xb + (size_t)row * Cc + c * 4);
        }
        { int row = tid >> 2, c = tid & 3;
          CP16(sptr(&Bs[0][row][c * 4]), gwt + (size_t)row * 16 + c * 4); }
        CP_COMMIT;
    }

    for (int it = 0; it < 24; it++) {
        const int buf = it & 1;
        if (it < 23) {
            const int kc = (it + 1) * 32;
            #pragma unroll
            for (int j = 0; j < 4; j++) {
                int idx = tid + j * 128, row = idx >> 3, c = idx & 7;
                CP16(sptr(&As[buf ^ 1][row][c * 4]), xb + (size_t)row * Cc + kc + c * 4);
            }
            { int row = tid >> 2, c = tid & 3;
              CP16(sptr(&Bs[buf ^ 1][row][c * 4]), gwt + (size_t)(kc + row) * 16 + c * 4); }
            CP_COMMIT;
            CP_WAIT1;
        } else {
            CP_WAIT0;
        }
        __syncthreads();

        // emit bf16 x for this tile (side product; feeds fc1)
        #pragma unroll
        for (int j = 0; j < 4; j++) {
            int idx = tid + j * 128, row = idx >> 3, c = idx & 7;
            float4 v = *(const float4*)&As[buf][row][c * 4];
            size_t el = (((size_t)b * Nn + m0 + row) * Cc + it * 32 + c * 4);
            ((uint2*)g_xb)[el >> 2] = make_uint2(pkbf(v.x, v.y), pkbf(v.z, v.w));
        }

        #pragma unroll
        for (int s = 0; s < 4; s++) {
            unsigned a0 = __float_as_uint(As[buf][warp * 16 + g    ][s * 8 + tq]);
            unsigned a1 = __float_as_uint(As[buf][warp * 16 + g + 8][s * 8 + tq]);
            unsigned a2 = __float_as_uint(As[buf][warp * 16 + g    ][s * 8 + 4 + tq]);
            unsigned a3 = __float_as_uint(As[buf][warp * 16 + g + 8][s * 8 + 4 + tq]);
            unsigned b0c = __float_as_uint(Bs[buf][s * 8 + tq    ][g]);
            unsigned b1c = __float_as_uint(Bs[buf][s * 8 + 4 + tq][g]);
            unsigned b0n = __float_as_uint(Bs[buf][s * 8 + tq    ][8 + g]);
            unsigned b1n = __float_as_uint(Bs[buf][s * 8 + 4 + tq][8 + g]);
            mma_tf32(acc[0], a0, a1, a2, a3, b0c, b1c);
            mma_tf32(acc[1], a0, a1, a2, a3, b0n, b1n);
        }
        __syncthreads();
    }

    // epilogue: logits = clean + eps * (softplus(noise)+0.01), reduce over rows
    const int r0 = m0 + warp * 16 + g, r1 = r0 + 8;
    const int e0 = 2 * tq, e1 = e0 + 1;
    const float* eb = eps + (size_t)b * Nn * Ee;
    #define SPLUS(r) (((r) > 20.0f) ? (r) : log1pf(expf(r)))
    float s0 = (acc[0][0] + eb[r0 * 8 + e0] * (SPLUS(acc[1][0]) + 0.01f))
             + (acc[0][2] + eb[r1 * 8 + e0] * (SPLUS(acc[1][2]) + 0.01f));
    float s1 = (acc[0][1] + eb[r0 * 8 + e1] * (SPLUS(acc[1][1]) + 0.01f))
             + (acc[0][3] + eb[r1 * 8 + e1] * (SPLUS(acc[1][3]) + 0.01f));
    #pragma unroll
    for (int off = 16; off >= 4; off >>= 1) {
        s0 += __shfl_xor_sync(0xffffffffu, s0, off);
        s1 += __shfl_xor_sync(0xffffffffu, s1, off);
    }
    if (lane < 4) {
        atomicAdd(&g_sums[b * 8 + 2 * lane],     s0);
        atomicAdd(&g_sums[b * 8 + 2 * lane + 1], s1);
    }
}

// ---------------------------------------------------------------------------
// 2) top-2 + gate values
// ---------------------------------------------------------------------------
__global__ void topk_kernel() {
    int b = threadIdx.x;
    if (b >= Bb) return;
    float s[Ee];
    #pragma unroll
    for (int e = 0; e < Ee; e++) s[e] = g_sums[b * Ee + e];
    int i1 = 0; float v1 = s[0];
    #pragma unroll
    for (int e = 1; e < Ee; e++) if (s[e] > v1) { v1 = s[e]; i1 = e; }
    int i2 = -1; float v2 = -3.4e38f;
    #pragma unroll
    for (int e = 0; e < Ee; e++) if (e != i1 && s[e] > v2) { v2 = s[e]; i2 = e; }
    float d   = v1 - v2;
    float sc1 = d / (d + 1e-6f);
    float mx  = fmaxf(sc1, 0.0f);
    float e1  = expf(sc1 - mx), e2 = expf(0.0f - mx);
    float inv = 1.0f / (e1 + e2);
    g_sel[b * 2 + 0]  = i1;  g_sel[b * 2 + 1]  = i2;
    g_gate[b * 2 + 0] = e1 * inv;  g_gate[b * 2 + 1] = e2 * inv;
}

// ---------------------------------------------------------------------------
// 3) fc1: bf16 mma + cp.async. Per (b,slot): [1024x768]@[192x768]^T.
//    BM=64, BN=192 (full H), BK=32. 8 warps = 2m x 4n, warp 32x48.
//    Epilogue: +bias, exact gelu, *gate -> g_hb (bf16).
// ---------------------------------------------------------------------------
__device__ __forceinline__ void fc1_issue(unsigned (*As)[20], unsigned (*Bs)[20],
                                          const unsigned* Ag, const unsigned* Bg,
                                          int kw, int tid) {
    { int row = tid >> 2, c = tid & 3;
      CP16(sptr(&As[row][c * 4]), Ag + (size_t)row * 384 + kw + c * 4); }
    #pragma unroll
    for (int j = 0; j < 3; j++) {
        int idx = tid + j * 256, row = idx >> 2, c = idx & 3;
        CP16(sptr(&Bs[row][c * 4]), Bg + (size_t)row * 384 + kw + c * 4);
    }
    CP_COMMIT;
}

__global__ void __launch_bounds__(256, 2)
fc1_kernel(const float* __restrict__ b1v) {
    __shared__ unsigned As[2][64][20];    // bf16 pairs, 80B row stride: banks 20g+t CF
    __shared__ unsigned Bs[2][192][20];

    const int bs = blockIdx.y, b = bs >> 1, slot = bs & 1;
    const int e  = g_sel[b * 2 + slot];
    const float gt = g_gate[b * 2 + slot];
    const int m0 = blockIdx.x * 64;
    const unsigned* Ag = g_xb  + ((size_t)b * Nn + m0) * 384;  // word row stride 384
    const unsigned* Bg = g_w1b + (size_t)e * Hh * 384;

    const int tid = threadIdx.x, warp = tid >> 5, lane = tid & 31;
    const int g = lane >> 2, tq = lane & 3;
    const int wm = warp >> 2, wn = warp & 3;

    float acc[2][6][4] = {};

    fc1_issue(As[0], Bs[0], Ag, Bg, 0, tid);
    for (int it = 0; it < 24; it++) {
        const int buf = it & 1;
        if (it < 23) { fc1_issue(As[buf ^ 1], Bs[buf ^ 1], Ag, Bg, (it + 1) * 16, tid); CP_WAIT1; }
        else CP_WAIT0;
        __syncthreads();

        #pragma unroll
        for (int s = 0; s < 2; s++) {
            unsigned af[2][4];
            #pragma unroll
            for (int mi = 0; mi < 2; mi++) {
                int mr = wm * 32 + mi * 16 + g;
                af[mi][0] = As[buf][mr    ][s * 8 + tq];
                af[mi][1] = As[buf][mr + 8][s * 8 + tq];
                af[mi][2] = As[buf][mr    ][s * 8 + 4 + tq];
                af[mi][3] = As[buf][mr + 8][s * 8 + 4 + tq];
            }
            unsigned bf[6][2];
            #pragma unroll
            for (int ni = 0; ni < 6; ni++) {
                int nr = wn * 48 + ni * 8 + g;
                bf[ni][0] = Bs[buf][nr][s * 8 + tq];
                bf[ni][1] = Bs[buf][nr][s * 8 + 4 + tq];
            }
            #pragma unroll
            for (int mi = 0; mi < 2; mi++)
                #pragma unroll
                for (int ni = 0; ni < 6; ni++)
                    mma_bf16(acc[mi][ni], af[mi], bf[ni]);
        }
        __syncthreads();
    }

    unsigned* hb = g_hb + ((size_t)(b * 2 + slot) * Nn) * 96;  // word row stride 96
    #pragma unroll
    for (int ni = 0; ni < 6; ni++) {
        int col = wn * 48 + ni * 8 + 2 * tq;
        float bi0 = b1v[e * Hh + col], bi1 = b1v[e * Hh + col + 1];
        #pragma unroll
        for (int mi = 0; mi < 2; mi++) {
            int r = m0 + wm * 32 + mi * 16 + g;
            float v0 = gelu_exact(acc[mi][ni][0] + bi0) * gt;
            float v1 = gelu_exact(acc[mi][ni][1] + bi1) * gt;
            float v2 = gelu_exact(acc[mi][ni][2] + bi0) * gt;
            float v3 = gelu_exact(acc[mi][ni][3] + bi1) * gt;
            hb[(size_t)r * 96 + (col >> 1)]       = pkbf(v0, v1);
            hb[(size_t)(r + 8) * 96 + (col >> 1)] = pkbf(v2, v3);
        }
    }
}

// ---------------------------------------------------------------------------
// 4) fc2: bf16 mma + cp.async over both slots (gate already in h).
//    Per b: [1024x192]@[768x192]^T x2. BM=64, BN=128, BK=32, 12 k-iters.
//    Epilogue: + gated biases + residual x (fp32).
// ---------------------------------------------------------------------------
__global__ void __launch_bounds__(256, 2)
fc2_kernel(const float* __restrict__ x,
           const float* __restrict__ b2,
           float* __restrict__ out) {
    __shared__ unsigned As[2][64][20];
    __shared__ unsigned Bs[2][128][20];

    const int b  = blockIdx.z;
    const int m0 = blockIdx.y * 64;
    const int n0 = blockIdx.x * 128;
    const int sel0 = g_sel[b * 2], sel1 = g_sel[b * 2 + 1];
    const float gt0 = g_gate[b * 2], gt1 = g_gate[b * 2 + 1];

    const unsigned* Ag0 = g_hb + ((size_t)(b * 2 + 0) * Nn + m0) * 96;
    const unsigned* Ag1 = g_hb + ((size_t)(b * 2 + 1) * Nn + m0) * 96;
    const unsigned* Bg0 = g_w2b + (size_t)sel0 * Cc * 96 + (size_t)n0 * 96;
    const unsigned* Bg1 = g_w2b + (size_t)sel1 * Cc * 96 + (size_t)n0 * 96;

    const int tid = threadIdx.x, warp = tid >> 5, lane = tid & 31;
    const int g = lane >> 2, tq = lane & 3;
    const int wm = warp >> 2, wn = warp & 3;

    float acc[2][4][4] = {};

    // issue helper inline (12 iters: it<6 -> slot0, else slot1; kw = (it%6)*16 words)
    #define FC2_ISSUE(IT, BUF)                                                          \
    {                                                                                   \
        const unsigned* Ag = ((IT) < 6) ? Ag0 : Ag1;                                    \
        const unsigned* Bg = ((IT) < 6) ? Bg0 : Bg1;                                    \
        int kw = ((IT) % 6) * 16;                                                       \
        { int row = tid >> 2, c = tid & 3;                                              \
          CP16(sptr(&As[BUF][row][c * 4]), Ag + (size_t)row * 96 + kw + c * 4); }       \
        _Pragma("unroll")                                                               \
        for (int j = 0; j < 2; j++) {                                                   \
            int idx = tid + j * 256, row = idx >> 2, c = idx & 3;                       \
            CP16(sptr(&Bs[BUF][row][c * 4]), Bg + (size_t)row * 96 + kw + c * 4);       \
        }                                                                               \
        CP_COMMIT;                                                                      \
    }

    FC2_ISSUE(0, 0);
    for (int it = 0; it < 12; it++) {
        const int buf = it & 1;
        if (it < 11) { FC2_ISSUE(it + 1, buf ^ 1); CP_WAIT1; }
        else CP_WAIT0;
        __syncthreads();

        #pragma unroll
        for (int s = 0; s < 2; s++) {
            unsigned af[2][4];
            #pragma unroll
            for (int mi = 0; mi < 2; mi++) {
                int mr = wm * 32 + mi * 16 + g;
                af[mi][0] = As[buf][mr    ][s * 8 + tq];
                af[mi][1] = As[buf][mr + 8][s * 8 + tq];
                af[mi][2] = As[buf][mr    ][s * 8 + 4 + tq];
                af[mi][3] = As[buf][mr + 8][s * 8 + 4 + tq];
            }
            unsigned bf[4][2];
            #pragma unroll
            for (int ni = 0; ni < 4; ni++) {
                int nr = wn * 32 + ni * 8 + g;
                bf[ni][0] = Bs[buf][nr][s * 8 + tq];
                bf[ni][1] = Bs[buf][nr][s * 8 + 4 + tq];
            }
            #pragma unroll
            for (int mi = 0; mi < 2; mi++)
                #pragma unroll
                for (int ni = 0; ni < 4; ni++)
                    mma_bf16(acc[mi][ni], af[mi], bf[ni]);
        }
        __syncthreads();
    }

    #pragma unroll
    for (int ni = 0; ni < 4; ni++) {
        int col = n0 + wn * 32 + ni * 8 + 2 * tq;
        float bi0 = gt0 * b2[sel0 * Cc + col]     + gt1 * b2[sel1 * Cc + col];
        float bi1 = gt0 * b2[sel0 * Cc + col + 1] + gt1 * b2[sel1 * Cc + col + 1];
        #pragma unroll
        for (int mi = 0; mi < 2; mi++) {
            int r = m0 + wm * 32 + mi * 16 + g;
            {
                float2 xv = *(const float2*)&x[((size_t)b * Nn + r) * Cc + col];
                *(float2*)&out[((size_t)b * Nn + r) * Cc + col] =
                    make_float2(xv.x + acc[mi][ni][0] + bi0,
                                xv.y + acc[mi][ni][1] + bi1);
            }
            {
                float2 xv = *(const float2*)&x[((size_t)b * Nn + r + 8) * Cc + col];
                *(float2*)&out[((size_t)b * Nn + r + 8) * Cc + col] =
                    make_float2(xv.x + acc[mi][ni][2] + bi0,
                                xv.y + acc[mi][ni][3] + bi1);
            }
        }
    }
}

// ---------------------------------------------------------------------------
extern "C" void kernel_launch(void* const* d_in, const int* in_sizes, int n_in,
                              void* d_out, int out_size) {
    const float* x        = (const float*)d_in[0];
    const int*   task_ids = (const int*)  d_in[1];
    const float* eps      = (const float*)d_in[2];
    const float* gate_w   = (const float*)d_in[3];
    const float* fc1_w    = (const float*)d_in[4];
    const float* fc1_b    = (const float*)d_in[5];
    const float* fc2_w    = (const float*)d_in[6];
    const float* fc2_b    = (const float*)d_in[7];
    float* out = (float*)d_out;

    prep_kernel<<<2 * (Ee * Hh * Cc / 4) / 256, 256>>>(fc1_w, fc2_w);
    gate_kernel<<<dim3(Nn / 64, Bb), 128>>>(x, task_ids, eps, gate_w);
    topk_kernel<<<1, 32>>>();
    fc1_kernel<<<dim3(Nn / 64, Bb * Kk), 256>>>(fc1_b);
    fc2_kernel<<<dim3(Cc / 128, Nn / 64, Bb), 256>>>(x, fc2_b, out);
}

// round 11
// speedup vs baseline: 5.3916x; 1.2495x over previous
#include <cuda_runtime.h>
#include <cuda_bf16.h>
#include <math.h>

#define Bb 16
#define Nn 1024
#define Cc 768
#define Ee 8
#define Hh 192
#define Kk 2

// Persistent device scratch (no allocations allowed)
__device__ float    g_sums[Bb * Ee];
__device__ int      g_sel[Bb * Kk];
__device__ float    g_gate[Bb * Kk];
__device__ unsigned g_xb [Bb * Nn * Cc / 2];       // x as bf16 pairs (25 MB)
__device__ unsigned g_w1b[Ee * Hh * Cc / 2];       // fc1_w bf16
__device__ unsigned g_w2b[Ee * Cc * Hh / 2];       // fc2_w bf16
__device__ unsigned g_hb [(size_t)Bb * Kk * Nn * Hh / 2];  // gated gelu(h) bf16

// ---------------- helpers ----------------
__device__ __forceinline__ unsigned sptr(const void* p) {
    return (unsigned)__cvta_generic_to_shared(p);
}
#define CP16(d, s) asm volatile("cp.async.cg.shared.global [%0], [%1], 16;\n" :: "r"(d), "l"(s))
#define CP_COMMIT  asm volatile("cp.async.commit_group;\n")
#define CP_WAIT1   asm volatile("cp.async.wait_group 1;\n")
#define CP_WAIT0   asm volatile("cp.async.wait_group 0;\n")

__device__ __forceinline__ unsigned pkbf(float lo, float hi) {
    unsigned u;
    asm("cvt.rn.bf16x2.f32 %0, %1, %2;" : "=r"(u) : "f"(hi), "f"(lo));
    return u;
}

__device__ __forceinline__ void ldsm4(unsigned& r0, unsigned& r1, unsigned& r2, unsigned& r3,
                                      unsigned addr) {
    asm volatile("ldmatrix.sync.aligned.m8n8.x4.shared.b16 {%0,%1,%2,%3}, [%4];"
                 : "=r"(r0), "=r"(r1), "=r"(r2), "=r"(r3) : "r"(addr));
}

__device__ __forceinline__ void mma_bf16(float* c, const unsigned* a, const unsigned* b) {
    asm volatile(
        "mma.sync.aligned.m16n8k16.row.col.f32.bf16.bf16.f32 "
        "{%0,%1,%2,%3},{%4,%5,%6,%7},{%8,%9},{%0,%1,%2,%3};"
        : "+f"(c[0]), "+f"(c[1]), "+f"(c[2]), "+f"(c[3])
        : "r"(a[0]), "r"(a[1]), "r"(a[2]), "r"(a[3]), "r"(b[0]), "r"(b[1]));
}

__device__ __forceinline__ void mma_tf32(float* c, unsigned a0, unsigned a1, unsigned a2,
                                         unsigned a3, unsigned b0, unsigned b1) {
    asm volatile(
        "mma.sync.aligned.m16n8k8.row.col.f32.tf32.tf32.f32 "
        "{%0,%1,%2,%3},{%4,%5,%6,%7},{%8,%9},{%0,%1,%2,%3};"
        : "+f"(c[0]), "+f"(c[1]), "+f"(c[2]), "+f"(c[3])
        : "r"(a0), "r"(a1), "r"(a2), "r"(a3), "r"(b0), "r"(b1));
}

__device__ __forceinline__ float gelu_exact(float v) {
    return 0.5f * v * (1.0f + erff(v * 0.70710678118654752f));
}

// ---------------------------------------------------------------------------
// 0) prep: zero g_sums + convert fc1_w / fc2_w to bf16
// ---------------------------------------------------------------------------
__global__ void prep_kernel(const float* __restrict__ w1, const float* __restrict__ w2) {
    int i = blockIdx.x * 256 + threadIdx.x;
    if (i < Bb * Ee) g_sums[i] = 0.0f;
    const int NF4 = Ee * Hh * Cc / 4;
    if (i < NF4) {
        float4 v = ((const float4*)w1)[i];
        ((uint2*)g_w1b)[i] = make_uint2(pkbf(v.x, v.y), pkbf(v.z, v.w));
    } else if (i < 2 * NF4) {
        int j = i - NF4;
        float4 v = ((const float4*)w2)[j];
        ((uint2*)g_w2b)[j] = make_uint2(pkbf(v.x, v.y), pkbf(v.z, v.w));
    }
}

// ---------------------------------------------------------------------------
// 1) gate: tf32 mma, 3-stage cp.async, 1 sync/iter; emits bf16 x side product.
// ---------------------------------------------------------------------------
__global__ void gate_kernel(const float* __restrict__ x,
                            const int*   __restrict__ task_ids,
                            const float* __restrict__ eps,
                            const float* __restrict__ gate_w) {
    __shared__ float As[3][64][36];
    __shared__ float Bs[3][32][24];

    const int b  = blockIdx.y;
    const int m0 = blockIdx.x * 64;
    const int t_id = task_ids[b];
    const float* gwt = gate_w + (size_t)t_id * Cc * 16;
    const float* xb  = x + ((size_t)b * Nn + m0) * Cc;

    const int tid = threadIdx.x, warp = tid >> 5, lane = tid & 31;
    const int g = lane >> 2, tq = lane & 3;

    float acc[2][4] = {};

    #define GATE_ISSUE(T, BUF)                                                       \
    {                                                                                \
        const int kc = (T) * 32;                                                     \
        _Pragma("unroll")                                                            \
        for (int j = 0; j < 4; j++) {                                                \
            int idx = tid + j * 128, row = idx >> 3, c = idx & 7;                    \
            CP16(sptr(&As[BUF][row][c * 4]), xb + (size_t)row * Cc + kc + c * 4);    \
        }                                                                            \
        { int row = tid >> 2, c = tid & 3;                                           \
          CP16(sptr(&Bs[BUF][row][c * 4]), gwt + (size_t)(kc + row) * 16 + c * 4); } \
        CP_COMMIT;                                                                   \
    }

    GATE_ISSUE(0, 0);
    GATE_ISSUE(1, 1);

    for (int it = 0; it < 24; it++) {
        const int buf = it % 3;
        if (it == 23) { CP_WAIT0; } else { CP_WAIT1; }   // tail must fully drain
        __syncthreads();
        if (it + 2 < 24) GATE_ISSUE(it + 2, (it + 2) % 3);

        // emit bf16 x for this tile
        #pragma unroll
        for (int j = 0; j < 4; j++) {
            int idx = tid + j * 128, row = idx >> 3, c = idx & 7;
            float4 v = *(const float4*)&As[buf][row][c * 4];
            size_t el = (((size_t)b * Nn + m0 + row) * Cc + it * 32 + c * 4);
            ((uint2*)g_xb)[el >> 2] = make_uint2(pkbf(v.x, v.y), pkbf(v.z, v.w));
        }

        #pragma unroll
        for (int s = 0; s < 4; s++) {
            unsigned a0 = __float_as_uint(As[buf][warp * 16 + g    ][s * 8 + tq]);
            unsigned a1 = __float_as_uint(As[buf][warp * 16 + g + 8][s * 8 + tq]);
            unsigned a2 = __float_as_uint(As[buf][warp * 16 + g    ][s * 8 + 4 + tq]);
            unsigned a3 = __float_as_uint(As[buf][warp * 16 + g + 8][s * 8 + 4 + tq]);
            unsigned b0c = __float_as_uint(Bs[buf][s * 8 + tq    ][g]);
            unsigned b1c = __float_as_uint(Bs[buf][s * 8 + 4 + tq][g]);
            unsigned b0n = __float_as_uint(Bs[buf][s * 8 + tq    ][8 + g]);
            unsigned b1n = __float_as_uint(Bs[buf][s * 8 + 4 + tq][8 + g]);
            mma_tf32(acc[0], a0, a1, a2, a3, b0c, b1c);
            mma_tf32(acc[1], a0, a1, a2, a3, b0n, b1n);
        }
    }

    const int r0 = m0 + warp * 16 + g, r1 = r0 + 8;
    const int e0 = 2 * tq, e1 = e0 + 1;
    const float* eb = eps + (size_t)b * Nn * Ee;
    #define SPLUS(r) (((r) > 20.0f) ? (r) : log1pf(expf(r)))
    float s0 = (acc[0][0] + eb[r0 * 8 + e0] * (SPLUS(acc[1][0]) + 0.01f))
             + (acc[0][2] + eb[r1 * 8 + e0] * (SPLUS(acc[1][2]) + 0.01f));
    float s1 = (acc[0][1] + eb[r0 * 8 + e1] * (SPLUS(acc[1][1]) + 0.01f))
             + (acc[0][3] + eb[r1 * 8 + e1] * (SPLUS(acc[1][3]) + 0.01f));
    #pragma unroll
    for (int off = 16; off >= 4; off >>= 1) {
        s0 += __shfl_xor_sync(0xffffffffu, s0, off);
        s1 += __shfl_xor_sync(0xffffffffu, s1, off);
    }
    if (lane < 4) {
        atomicAdd(&g_sums[b * 8 + 2 * lane],     s0);
        atomicAdd(&g_sums[b * 8 + 2 * lane + 1], s1);
    }
}

// ---------------------------------------------------------------------------
// 2) top-2 + gate values
// ---------------------------------------------------------------------------
__global__ void topk_kernel() {
    int b = threadIdx.x;
    if (b >= Bb) return;
    float s[Ee];
    #pragma unroll
    for (int e = 0; e < Ee; e++) s[e] = g_sums[b * Ee + e];
    int i1 = 0; float v1 = s[0];
    #pragma unroll
    for (int e = 1; e < Ee; e++) if (s[e] > v1) { v1 = s[e]; i1 = e; }
    int i2 = -1; float v2 = -3.4e38f;
    #pragma unroll
    for (int e = 0; e < Ee; e++) if (e != i1 && s[e] > v2) { v2 = s[e]; i2 = e; }
    float d   = v1 - v2;
    float sc1 = d / (d + 1e-6f);
    float mx  = fmaxf(sc1, 0.0f);
    float e1  = expf(sc1 - mx), e2 = expf(0.0f - mx);
    float inv = 1.0f / (e1 + e2);
    g_sel[b * 2 + 0]  = i1;  g_sel[b * 2 + 1]  = i2;
    g_gate[b * 2 + 0] = e1 * inv;  g_gate[b * 2 + 1] = e2 * inv;
}

// ---------------------------------------------------------------------------
// 3) fc1: bf16 mma + ldmatrix + 3-stage cp.async (1 sync/iter).
//    Per (b,slot): [1024x768]@[192x768]^T. BM=64, BN=192, BK=32.
//    8 warps = 2m x 4n, warp 32x48. Epilogue: +bias, gelu, *gate -> g_hb.
// ---------------------------------------------------------------------------
#define F1_ABUF (64 * 20 * 4)
#define F1_BBUF (192 * 20 * 4)

__global__ void __launch_bounds__(256, 2)
fc1_kernel(const float* __restrict__ b1v) {
    __shared__ unsigned As[3][64][20];    // 80B row stride: ldmatrix phases CF
    __shared__ unsigned Bs[3][192][20];

    const int bs = blockIdx.y, b = bs >> 1, slot = bs & 1;
    const int e  = g_sel[b * 2 + slot];
    const float gt = g_gate[b * 2 + slot];
    const int m0 = blockIdx.x * 64;
    const unsigned* Ag = g_xb  + ((size_t)b * Nn + m0) * 384;
    const unsigned* Bg = g_w1b + (size_t)e * Hh * 384;

    const int tid = threadIdx.x, warp = tid >> 5, lane = tid & 31;
    const int g = lane >> 2, tq = lane & 3;
    const int wm = warp >> 2, wn = warp & 3;

    float acc[2][6][4] = {};

    #define FC1_ISSUE(T, BUF)                                                           \
    {                                                                                   \
        const int kw = (T) * 16;                                                        \
        { int row = tid >> 2, c = tid & 3;                                              \
          CP16(sptr(&As[BUF][row][c * 4]), Ag + (size_t)row * 384 + kw + c * 4); }      \
        _Pragma("unroll")                                                               \
        for (int j = 0; j < 3; j++) {                                                   \
            int idx = tid + j * 256, row = idx >> 2, c = idx & 3;                       \
            CP16(sptr(&Bs[BUF][row][c * 4]), Bg + (size_t)row * 384 + kw + c * 4);      \
        }                                                                               \
        CP_COMMIT;                                                                      \
    }

    // ldmatrix lane bases (buf term added per iter)
    const unsigned aS = sptr(&As[0][0][0]);
    const unsigned bS = sptr(&Bs[0][0][0]);
    const unsigned aLane = aS + (unsigned)((wm * 32 + (lane & 15)) * 80 + ((lane & 16) ? 16 : 0));
    const unsigned bLane = bS + (unsigned)((wn * 48 + ((lane & 16) >> 1) + (lane & 7)) * 80
                                           + ((lane & 8) ? 16 : 0));

    FC1_ISSUE(0, 0);
    FC1_ISSUE(1, 1);

    for (int it = 0; it < 24; it++) {
        const int buf = it % 3;
        if (it == 23) { CP_WAIT0; } else { CP_WAIT1; }   // tail must fully drain
        __syncthreads();
        if (it + 2 < 24) FC1_ISSUE(it + 2, (it + 2) % 3);

        const unsigned aB = aLane + (unsigned)(buf * F1_ABUF);
        const unsigned bB = bLane + (unsigned)(buf * F1_BBUF);
        #pragma unroll
        for (int s = 0; s < 2; s++) {
            unsigned af[2][4];
            ldsm4(af[0][0], af[0][1], af[0][2], af[0][3], aB + s * 32);
            ldsm4(af[1][0], af[1][1], af[1][2], af[1][3], aB + 16 * 80 + s * 32);
            unsigned bfr[3][4];
            #pragma unroll
            for (int p = 0; p < 3; p++)
                ldsm4(bfr[p][0], bfr[p][1], bfr[p][2], bfr[p][3], bB + p * 16 * 80 + s * 32);
            #pragma unroll
            for (int mi = 0; mi < 2; mi++)
                #pragma unroll
                for (int ni = 0; ni < 6; ni++)
                    mma_bf16(acc[mi][ni], af[mi], &bfr[ni >> 1][(ni & 1) * 2]);
        }
    }

    unsigned* hb = g_hb + ((size_t)(b * 2 + slot) * Nn) * 96;
    #pragma unroll
    for (int ni = 0; ni < 6; ni++) {
        int col = wn * 48 + ni * 8 + 2 * tq;
        float bi0 = b1v[e * Hh + col], bi1 = b1v[e * Hh + col + 1];
        #pragma unroll
        for (int mi = 0; mi < 2; mi++) {
            int r = m0 + wm * 32 + mi * 16 + g;
            float v0 = gelu_exact(acc[mi][ni][0] + bi0) * gt;
            float v1 = gelu_exact(acc[mi][ni][1] + bi1) * gt;
            float v2 = gelu_exact(acc[mi][ni][2] + bi0) * gt;
            float v3 = gelu_exact(acc[mi][ni][3] + bi1) * gt;
            hb[(size_t)r * 96 + (col >> 1)]       = pkbf(v0, v1);
            hb[(size_t)(r + 8) * 96 + (col >> 1)] = pkbf(v2, v3);
        }
    }
}

// ---------------------------------------------------------------------------
// 4) fc2: bf16 mma + ldmatrix + 3-stage cp.async over both slots.
//    Per b: [1024x192]@[768x192]^T x2. BM=64, BN=128, 12 k-iters.
// ---------------------------------------------------------------------------
#define F2_ABUF (64 * 20 * 4)
#define F2_BBUF (128 * 20 * 4)

__global__ void __launch_bounds__(256, 2)
fc2_kernel(const float* __restrict__ x,
           const float* __restrict__ b2,
           float* __restrict__ out) {
    __shared__ unsigned As[3][64][20];
    __shared__ unsigned Bs[3][128][20];

    const int b  = blockIdx.z;
    const int m0 = blockIdx.y * 64;
    const int n0 = blockIdx.x * 128;
    const int sel0 = g_sel[b * 2], sel1 = g_sel[b * 2 + 1];
    const float gt0 = g_gate[b * 2], gt1 = g_gate[b * 2 + 1];

    const unsigned* Ag0 = g_hb + ((size_t)(b * 2 + 0) * Nn + m0) * 96;
    const unsigned* Ag1 = g_hb + ((size_t)(b * 2 + 1) * Nn + m0) * 96;
    const unsigned* Bg0 = g_w2b + ((size_t)sel0 * Cc + n0) * 96;
    const unsigned* Bg1 = g_w2b + ((size_t)sel1 * Cc + n0) * 96;

    const int tid = threadIdx.x, warp = tid >> 5, lane = tid & 31;
    const int g = lane >> 2, tq = lane & 3;
    const int wm = warp >> 2, wn = warp & 3;

    float acc[2][4][4] = {};

    #define FC2_ISSUE(T, BUF)                                                           \
    {                                                                                   \
        const unsigned* Ag = ((T) < 6) ? Ag0 : Ag1;                                     \
        const unsigned* Bg = ((T) < 6) ? Bg0 : Bg1;                                     \
        int kw = ((T) % 6) * 16;                                                        \
        { int row = tid >> 2, c = tid & 3;                                              \
          CP16(sptr(&As[BUF][row][c * 4]), Ag + (size_t)row * 96 + kw + c * 4); }       \
        _Pragma("unroll")                                                               \
        for (int j = 0; j < 2; j++) {                                                   \
            int idx = tid + j * 256, row = idx >> 2, c = idx & 3;                       \
            CP16(sptr(&Bs[BUF][row][c * 4]), Bg + (size_t)row * 96 + kw + c * 4);       \
        }                                                                               \
        CP_COMMIT;                                                                      \
    }

    const unsigned aS = sptr(&As[0][0][0]);
    const unsigned bS = sptr(&Bs[0][0][0]);
    const unsigned aLane = aS + (unsigned)((wm * 32 + (lane & 15)) * 80 + ((lane & 16) ? 16 : 0));
    const unsigned bLane = bS + (unsigned)((wn * 32 + ((lane & 16) >> 1) + (lane & 7)) * 80
                                           + ((lane & 8) ? 16 : 0));

    FC2_ISSUE(0, 0);
    FC2_ISSUE(1, 1);

    for (int it = 0; it < 12; it++) {
        const int buf = it % 3;
        if (it == 11) { CP_WAIT0; } else { CP_WAIT1; }   // tail must fully drain
        __syncthreads();
        if (it + 2 < 12) FC2_ISSUE(it + 2, (it + 2) % 3);

        const unsigned aB = aLane + (unsigned)(buf * F2_ABUF);
        const unsigned bB = bLane + (unsigned)(buf * F2_BBUF);
        #pragma unroll
        for (int s = 0; s < 2; s++) {
            unsigned af[2][4];
            ldsm4(af[0][0], af[0][1], af[0][2], af[0][3], aB + s * 32);
            ldsm4(af[1][0], af[1][1], af[1][2], af[1][3], aB + 16 * 80 + s * 32);
            unsigned bfr[2][4];
            #pragma unroll
            for (int p = 0; p < 2; p++)
                ldsm4(bfr[p][0], bfr[p][1], bfr[p][2], bfr[p][3], bB + p * 16 * 80 + s * 32);
            #pragma unroll
            for (int mi = 0; mi < 2; mi++)
                #pragma unroll
                for (int ni = 0; ni < 4; ni++)
                    mma_bf16(acc[mi][ni], af[mi], &bfr[ni >> 1][(ni & 1) * 2]);
        }
    }

    #pragma unroll
    for (int ni = 0; ni < 4; ni++) {
        int col = n0 + wn * 32 + ni * 8 + 2 * tq;
        float bi0 = gt0 * b2[sel0 * Cc + col]     + gt1 * b2[sel1 * Cc + col];
        float bi1 = gt0 * b2[sel0 * Cc + col + 1] + gt1 * b2[sel1 * Cc + col + 1];
        #pragma unroll
        for (int mi = 0; mi < 2; mi++) {
            int r = m0 + wm * 32 + mi * 16 + g;
            {
                float2 xv = *(const float2*)&x[((size_t)b * Nn + r) * Cc + col];
                *(float2*)&out[((size_t)b * Nn + r) * Cc + col] =
                    make_float2(xv.x + acc[mi][ni][0] + bi0,
                                xv.y + acc[mi][ni][1] + bi1);
            }
            {
                float2 xv = *(const float2*)&x[((size_t)b * Nn + r + 8) * Cc + col];
                *(float2*)&out[((size_t)b * Nn + r + 8) * Cc + col] =
                    make_float2(xv.x + acc[mi][ni][2] + bi0,
                                xv.y + acc[mi][ni][3] + bi1);
            }
        }
    }
}

// ---------------------------------------------------------------------------
extern "C" void kernel_launch(void* const* d_in, const int* in_sizes, int n_in,
                              void* d_out, int out_size) {
    const float* x        = (const float*)d_in[0];
    const int*   task_ids = (const int*)  d_in[1];
    const float* eps      = (const float*)d_in[2];
    const float* gate_w   = (const float*)d_in[3];
    const float* fc1_w    = (const float*)d_in[4];
    const float* fc1_b    = (const float*)d_in[5];
    const float* fc2_w    = (const float*)d_in[6];
    const float* fc2_b    = (const float*)d_in[7];
    float* out = (float*)d_out;

    prep_kernel<<<2 * (Ee * Hh * Cc / 4) / 256, 256>>>(fc1_w, fc2_w);
    gate_kernel<<<dim3(Nn / 64, Bb), 128>>>(x, task_ids, eps, gate_w);
    topk_kernel<<<1, 32>>>();
    fc1_kernel<<<dim3(Nn / 64, Bb * Kk), 256>>>(fc1_b);
    fc2_kernel<<<dim3(Cc / 128, Nn / 64, Bb), 256>>>(x, fc2_b, out);
}